// round 14
// baseline (speedup 1.0000x reference)
#include <cuda_runtime.h>
#include <cstdint>
#include <cstddef>

#define T_SEQ 384
#define PRE_W 2048
#define ROWS_TOT 768

__device__ float g_pre0[ROWS_TOT * PRE_W];
__device__ float g_pre1[ROWS_TOT * PRE_W];
__device__ float g_x1  [ROWS_TOT * 512];
__device__ float g_lout[ROWS_TOT * 512];
__device__ float g_h1  [ROWS_TOT * 1024];
__device__ float g_h2  [ROWS_TOT * 512];
__device__ float g_u   [ROWS_TOT * 1024];
__device__ float g_W3s [1024 * 512];
__device__ float g_b1s [2048];

__device__ __forceinline__ float tanh_fast(float x) {
    float y; asm("tanh.approx.f32 %0, %1;" : "=f"(y) : "f"(x)); return y;
}
__device__ __forceinline__ float fsig(float x)  { return fmaf(0.5f, tanh_fast(0.5f * x), 0.5f); }

#define MBAR_WAIT(mba, par) do {                                              \
    uint32_t _go;                                                             \
    asm volatile("{\n\t.reg .pred P;\n\t"                                     \
      "mbarrier.try_wait.parity.acquire.cluster.shared::cta.b64 P, [%1], %2, 0x989680;\n\t" \
      "selp.b32 %0, 1, 0, P;\n\t}" : "=r"(_go) : "r"(mba), "r"(par) : "memory"); \
    while (!_go) {                                                            \
      asm volatile("{\n\t.reg .pred P;\n\t"                                   \
        "mbarrier.try_wait.parity.acquire.cluster.shared::cta.b64 P, [%1], %2, 0x989680;\n\t" \
        "selp.b32 %0, 1, 0, P;\n\t}" : "=r"(_go) : "r"(mba), "r"(par) : "memory"); \
    }                                                                         \
} while (0)

// W3s[n][k] = W3[n][k] + W3[n][512+k]; b1s = bih1 + bhh1
__global__ void prep_kernel(const float* __restrict__ W3,
                            const float* __restrict__ bih1, const float* __restrict__ bhh1) {
    int idx = blockIdx.x * 256 + threadIdx.x;
    for (int i = idx; i < 1024 * 512; i += gridDim.x * 256) {
        int n = i >> 9, k = i & 511;
        g_W3s[i] = W3[n * 1024 + k] + W3[n * 1024 + 512 + k];
    }
    if (idx < 2048) g_b1s[idx] = bih1[idx] + bhh1[idx];
}

__global__ void pre0_kernel(const float* __restrict__ vr, const float* __restrict__ vl,
                            const float* __restrict__ Wih0,
                            const float* __restrict__ bih0, const float* __restrict__ bhh0) {
    __shared__ float vs[22];
    int row = blockIdx.x;
    int col = blockIdx.y * 128 + threadIdx.x;
    int seq = (row >= 384) ? 1 : 0;
    int t = row - seq * 384;
    const float* v = seq ? vl : vr;
    if (threadIdx.x < 22) vs[threadIdx.x] = v[t * 22 + threadIdx.x];
    __syncthreads();
    const float* w = Wih0 + (size_t)col * 22;
    float acc = bih0[col] + bhh0[col];
#pragma unroll
    for (int k = 0; k < 22; k++) acc += vs[k] * w[k];
    g_pre0[(size_t)row * PRE_W + col] = acc;
}

// 4 chains (seq,dir), 8-CTA cluster per chain. rank owns hidden units [32r, 32r+32).
// R13 structure: scalar FFMA dot, single-warp mbarrier wait + __syncthreads release,
// warp0 epilogue, warp-wide coalesced DSMEM broadcast, hoisted mapa, last-step skip,
// exit cluster fence. R14 deltas: MUFU.TANH activations; gates stored transposed
// (gates[e*4+g]) so warp0 reads 4 gates with one LDS.128.
__global__ void __cluster_dims__(8, 1, 1) __launch_bounds__(512, 1)
lstm_kernel(const float* __restrict__ Whh, int layer) {
    __shared__ __align__(16) float hbuf[2][4 * 72];   // per-seg stride 72 floats (288B)
    __shared__ __align__(16) float gates[128];        // transposed: [e][g]
    __shared__ __align__(8) unsigned long long mb[2];

    const float* pre = layer ? g_pre1 : g_pre0;
    float* outp      = layer ? g_lout : g_x1;

    int tid = threadIdx.x;
    int rank = blockIdx.x & 7;
    int chain = blockIdx.x >> 3;
    int seq = chain >> 1, dir = chain & 1;
    int out = tid >> 2, seg = tid & 3;
    int gidx = out >> 5, e = out & 31;
    int row = gidx * 256 + rank * 32 + e;

    // 64 scalar weights in registers
    float w[64];
    {
        const float* wp = Whh + ((size_t)dir * 1024 + row) * 256 + seg * 64;
#pragma unroll
        for (int j = 0; j < 64; j += 4) {
            float4 t4 = *(const float4*)(wp + j);
            w[j] = t4.x; w[j+1] = t4.y; w[j+2] = t4.z; w[j+3] = t4.w;
        }
    }
    for (int i = tid; i < 2 * 4 * 72; i += 512) ((float*)hbuf)[i] = 0.0f;
    if (tid == 0) {
        uint32_t m0 = (uint32_t)__cvta_generic_to_shared(&mb[0]);
        asm volatile("mbarrier.init.shared.b64 [%0], 8;" :: "r"(m0) : "memory");
        asm volatile("mbarrier.init.shared.b64 [%0], 8;" :: "r"(m0 + 8) : "memory");
    }
    __syncthreads();
    asm volatile("barrier.cluster.arrive.aligned;" ::: "memory");
    asm volatile("barrier.cluster.wait.aligned;"   ::: "memory");

    uint32_t mbLocal = (uint32_t)__cvta_generic_to_shared(&mb[0]);
    // hoisted remote addresses (warp0 lanes only):
    //   radr[r] = address of MY h slot inside peer r's hbuf[0]
    //   rmbL    = peer (tid)'s mb[0]  (lanes 0-7)
    uint32_t radr[8];
    uint32_t rmbL = 0;
    if (tid < 32) {
        int k = rank * 32 + tid;
        uint32_t loc = (uint32_t)__cvta_generic_to_shared(
            &hbuf[0][(k >> 6) * 72 + (k & 63)]);
#pragma unroll
        for (int r = 0; r < 8; r++)
            asm("mapa.shared::cluster.u32 %0, %1, %2;" : "=r"(radr[r]) : "r"(loc), "r"(r));
        if (tid < 8)
            asm("mapa.shared::cluster.u32 %0, %1, %2;" : "=r"(rmbL) : "r"(mbLocal), "r"(tid));
    }

    float c = 0.0f;
    const float* preBase = pre + (size_t)(seq * T_SEQ) * PRE_W + dir * 1024 + row;
    float* outBase = outp + (size_t)(seq * T_SEQ) * 512 + dir * 256 + rank * 32;
    int ph0 = 0, ph1 = 0;

    int tt0 = dir ? (T_SEQ - 1) : 0;
    float pv = __ldg(preBase + (size_t)tt0 * PRE_W);

    for (int t = 0; t < T_SEQ; t++) {
        int b = t & 1;
        if (t > 0) {
            if (tid < 32) {                       // single-warp wait
                uint32_t mba = mbLocal + (uint32_t)(b * 8);
                int par = b ? ph1 : ph0;
                MBAR_WAIT(mba, par);
            }
            if (b) ph1 ^= 1; else ph0 ^= 1;
            __syncthreads();                      // release all warps; orders h reads
        }
        int tt = dir ? (T_SEQ - 1 - t) : t;
        float pvn = 0.0f;
        if (t + 1 < T_SEQ) {
            int ttn = dir ? (T_SEQ - 2 - t) : (t + 1);
            pvn = __ldg(preBase + (size_t)ttn * PRE_W);
        }

        // scalar-FFMA inner loop: 16x float4 LDS, 64 FFMA, 4 indep chains
        const float4* hp = (const float4*)&hbuf[b][seg * 72];
        float a0 = 0.f, a1 = 0.f, a2 = 0.f, a3 = 0.f;
#pragma unroll
        for (int j = 0; j < 16; j++) {
            float4 hv = hp[j];
            a0 += w[4*j+0] * hv.x;
            a1 += w[4*j+1] * hv.y;
            a2 += w[4*j+2] * hv.z;
            a3 += w[4*j+3] * hv.w;
        }
        float acc = (a0 + a1) + (a2 + a3);
        acc += __shfl_xor_sync(0xffffffffu, acc, 1);
        acc += __shfl_xor_sync(0xffffffffu, acc, 2);
        float x = acc + pv;
        float av = (gidx == 2) ? tanh_fast(x) : fsig(x);
        if (seg == 0) gates[e * 4 + gidx] = av;   // transposed store
        __syncthreads();                          // gates barrier (also orders my h-reads
                                                  // before my arrivals below)
        if (tid < 32) {
            float4 g4 = *(const float4*)&gates[tid * 4];   // i,f,g,o in one LDS.128
            c = g4.y * c + g4.x * g4.z;
            float hv = g4.w * tanh_fast(c);
            if (t + 1 < T_SEQ) {
                uint32_t boff = (uint32_t)(((t + 1) & 1) * 1152);
                // warp-wide coalesced broadcast: iteration r sends 32 lanes' h (128B) to peer r
#pragma unroll
                for (int r = 0; r < 8; r++) {
                    asm volatile("st.shared::cluster.f32 [%0], %1;"
                                 :: "r"(radr[r] + boff), "f"(hv) : "memory");
                }
                if (tid < 8) {
                    asm volatile("mbarrier.arrive.release.cluster.shared::cluster.b64 _, [%0];"
                                 :: "r"(rmbL + (uint32_t)(((t + 1) & 1) * 8)) : "memory");
                }
            }
            outBase[(size_t)tt * 512 + tid] = hv;
        }
        pv = pvn;
    }
    // exit fence: no CTA may leave while remote stores could target peer SMEM
    asm volatile("barrier.cluster.arrive.aligned;" ::: "memory");
    asm volatile("barrier.cluster.wait.aligned;"   ::: "memory");
}

// C[M,N] = epi(A[M,K] @ B[N,K]^T). MODE 0:+bias  1:relu(+bias)  2:0.5*acc + (row<384?bias:0)
template <int MODE>
__global__ void __launch_bounds__(256) gemm_kernel(
    const float* __restrict__ A, const float* __restrict__ B, const float* __restrict__ bias,
    float* __restrict__ C, int M, int N, int K) {
    __shared__ __align__(16) float As[16][68];
    __shared__ __align__(16) float Bs[16][68];
    int tid = threadIdx.x;
    int bm = blockIdx.y * 64, bn = blockIdx.x * 64;
    int tx = tid & 15, ty = tid >> 4;
    int lr = tid >> 2, lc = (tid & 3) * 4;

    const float* Ap = A + (size_t)(bm + lr) * K + lc;
    const float* Bp = B + (size_t)(bn + lr) * K + lc;
    float acc[4][4] = {};
    float4 ra = *(const float4*)Ap;
    float4 rb4 = *(const float4*)Bp;
    int nk = K >> 4;
    for (int kt = 0; kt < nk; kt++) {
        As[lc+0][lr] = ra.x; As[lc+1][lr] = ra.y; As[lc+2][lr] = ra.z; As[lc+3][lr] = ra.w;
        Bs[lc+0][lr] = rb4.x; Bs[lc+1][lr] = rb4.y; Bs[lc+2][lr] = rb4.z; Bs[lc+3][lr] = rb4.w;
        __syncthreads();
        if (kt + 1 < nk) {
            ra  = *(const float4*)(Ap + (kt + 1) * 16);
            rb4 = *(const float4*)(Bp + (kt + 1) * 16);
        }
#pragma unroll
        for (int kk = 0; kk < 16; kk++) {
            float4 a4 = *(const float4*)&As[kk][ty * 4];
            float4 b4 = *(const float4*)&Bs[kk][tx * 4];
            acc[0][0] += a4.x*b4.x; acc[0][1] += a4.x*b4.y; acc[0][2] += a4.x*b4.z; acc[0][3] += a4.x*b4.w;
            acc[1][0] += a4.y*b4.x; acc[1][1] += a4.y*b4.y; acc[1][2] += a4.y*b4.z; acc[1][3] += a4.y*b4.w;
            acc[2][0] += a4.z*b4.x; acc[2][1] += a4.z*b4.y; acc[2][2] += a4.z*b4.z; acc[2][3] += a4.z*b4.w;
            acc[3][0] += a4.w*b4.x; acc[3][1] += a4.w*b4.y; acc[3][2] += a4.w*b4.z; acc[3][3] += a4.w*b4.w;
        }
        __syncthreads();
    }
    float bj0 = bias[bn + tx*4 + 0], bj1 = bias[bn + tx*4 + 1];
    float bj2 = bias[bn + tx*4 + 2], bj3 = bias[bn + tx*4 + 3];
#pragma unroll
    for (int i = 0; i < 4; i++) {
        int grow = bm + ty * 4 + i;
        float4 o;
        if (MODE == 0) {
            o.x = acc[i][0]+bj0; o.y = acc[i][1]+bj1; o.z = acc[i][2]+bj2; o.w = acc[i][3]+bj3;
        } else if (MODE == 1) {
            o.x = fmaxf(acc[i][0]+bj0, 0.f); o.y = fmaxf(acc[i][1]+bj1, 0.f);
            o.z = fmaxf(acc[i][2]+bj2, 0.f); o.w = fmaxf(acc[i][3]+bj3, 0.f);
        } else {
            float sc = (grow < 384) ? 1.f : 0.f;
            o.x = 0.5f*acc[i][0] + sc*bj0; o.y = 0.5f*acc[i][1] + sc*bj1;
            o.z = 0.5f*acc[i][2] + sc*bj2; o.w = 0.5f*acc[i][3] + sc*bj3;
        }
        *(float4*)&C[(size_t)grow * N + bn + tx * 4] = o;
    }
}

// d(i,j) = sum_h relu(u[i,h]+u[384+j,h])*(Wout[1,h]-Wout[0,h]) + db; out = {-l, d-l}, l=log1pexp(d)
__global__ void __launch_bounds__(256) pair_kernel(
    const float* __restrict__ Wout, const float* __restrict__ bout, float* __restrict__ outp) {
    __shared__ __align__(16) float urs[16][136];
    __shared__ __align__(16) float uls[16][136];
    __shared__ __align__(16) float dws[128];
    int tid = threadIdx.x;
    int bi = blockIdx.y * 16, bj = blockIdx.x * 16;
    int ti = tid >> 4, tj = tid & 15;
    int lr = tid >> 4, lc = (tid & 15) * 8;
    float d = bout[1] - bout[0];
    for (int hc = 0; hc < 1024; hc += 128) {
        __syncthreads();
        *(float4*)&urs[lr][lc]   = *(const float4*)&g_u[(size_t)(bi + lr) * 1024 + hc + lc];
        *(float4*)&urs[lr][lc+4] = *(const float4*)&g_u[(size_t)(bi + lr) * 1024 + hc + lc + 4];
        *(float4*)&uls[lr][lc]   = *(const float4*)&g_u[(size_t)(384 + bj + lr) * 1024 + hc + lc];
        *(float4*)&uls[lr][lc+4] = *(const float4*)&g_u[(size_t)(384 + bj + lr) * 1024 + hc + lc + 4];
        if (tid < 128) dws[tid] = Wout[1024 + hc + tid] - Wout[hc + tid];
        __syncthreads();
#pragma unroll 8
        for (int k = 0; k < 128; k += 4) {
            float4 a = *(const float4*)&urs[ti][k];
            float4 b = *(const float4*)&uls[tj][k];
            float4 w4 = *(const float4*)&dws[k];
            d += fmaxf(a.x + b.x, 0.f) * w4.x;
            d += fmaxf(a.y + b.y, 0.f) * w4.y;
            d += fmaxf(a.z + b.z, 0.f) * w4.z;
            d += fmaxf(a.w + b.w, 0.f) * w4.w;
        }
    }
    float m = fmaxf(d, 0.f);
    float l = m + __logf(__expf(0.f - m) + __expf(d - m));
    float2 o; o.x = -l; o.y = d - l;
    *(float2*)&outp[((size_t)(bi + ti) * 384 + (bj + tj)) * 2] = o;
}

extern "C" void kernel_launch(void* const* d_in, const int* in_sizes, int n_in,
                              void* d_out, int out_size) {
    const float* v_r  = (const float*)d_in[0];
    const float* v_l  = (const float*)d_in[1];
    const float* Wih0 = (const float*)d_in[2];
    const float* Whh0 = (const float*)d_in[3];
    const float* bih0 = (const float*)d_in[4];
    const float* bhh0 = (const float*)d_in[5];
    const float* Wih1 = (const float*)d_in[6];
    const float* Whh1 = (const float*)d_in[7];
    const float* bih1 = (const float*)d_in[8];
    const float* bhh1 = (const float*)d_in[9];
    const float* W1   = (const float*)d_in[10];
    const float* b1   = (const float*)d_in[11];
    const float* W2   = (const float*)d_in[12];
    const float* b2   = (const float*)d_in[13];
    const float* W3   = (const float*)d_in[14];
    const float* b3   = (const float*)d_in[15];
    const float* Wout = (const float*)d_in[16];
    const float* bout = (const float*)d_in[17];
    float* outp = (float*)d_out;

    void *p_x1, *p_lout, *p_h1, *p_h2, *p_u, *p_W3s, *p_b1s, *p_pre1;
    cudaGetSymbolAddress(&p_x1,   g_x1);
    cudaGetSymbolAddress(&p_lout, g_lout);
    cudaGetSymbolAddress(&p_h1,   g_h1);
    cudaGetSymbolAddress(&p_h2,   g_h2);
    cudaGetSymbolAddress(&p_u,    g_u);
    cudaGetSymbolAddress(&p_W3s,  g_W3s);
    cudaGetSymbolAddress(&p_b1s,  g_b1s);
    cudaGetSymbolAddress(&p_pre1, g_pre1);

    prep_kernel<<<148, 256>>>(W3, bih1, bhh1);
    pre0_kernel<<<dim3(ROWS_TOT, 16), 128>>>(v_r, v_l, Wih0, bih0, bhh0);
    lstm_kernel<<<32, 512>>>(Whh0, 0);
    gemm_kernel<0><<<dim3(32, 12), 256>>>((const float*)p_x1, Wih1, (const float*)p_b1s,
                                          (float*)p_pre1, 768, 2048, 512);
    lstm_kernel<<<32, 512>>>(Whh1, 1);
    gemm_kernel<1><<<dim3(16, 12), 256>>>((const float*)p_lout, W1, b1,
                                          (float*)p_h1, 768, 1024, 512);
    gemm_kernel<1><<<dim3(8, 12), 256>>>((const float*)p_h1, W2, b2,
                                         (float*)p_h2, 768, 512, 1024);
    gemm_kernel<2><<<dim3(16, 12), 256>>>((const float*)p_h2, (const float*)p_W3s, b3,
                                          (float*)p_u, 768, 1024, 512);
    pair_kernel<<<dim3(24, 24), 256>>>(Wout, bout, outp);
}

// round 15
// speedup vs baseline: 1.2193x; 1.2193x over previous
#include <cuda_runtime.h>
#include <cstdint>
#include <cstddef>

#define T_SEQ 384
#define PRE_W 2048
#define ROWS_TOT 768
#define CS 16   // cluster size (nonportable)

__device__ float g_pre0[ROWS_TOT * PRE_W];
__device__ float g_pre1[ROWS_TOT * PRE_W];
__device__ float g_x1  [ROWS_TOT * 512];
__device__ float g_lout[ROWS_TOT * 512];
__device__ float g_h1  [ROWS_TOT * 1024];
__device__ float g_h2  [ROWS_TOT * 512];
__device__ float g_u   [ROWS_TOT * 1024];
__device__ float g_W3s [1024 * 512];
__device__ float g_b1s [2048];

__device__ __forceinline__ float fsig(float x)  { return __fdividef(1.0f, 1.0f + __expf(-x)); }
__device__ __forceinline__ float ftanh_(float x){ return __fdividef(2.0f, 1.0f + __expf(-2.0f * x)) - 1.0f; }

#define MBAR_WAIT(mba, par) do {                                              \
    uint32_t _go;                                                             \
    asm volatile("{\n\t.reg .pred P;\n\t"                                     \
      "mbarrier.try_wait.parity.acquire.cluster.shared::cta.b64 P, [%1], %2, 0x989680;\n\t" \
      "selp.b32 %0, 1, 0, P;\n\t}" : "=r"(_go) : "r"(mba), "r"(par) : "memory"); \
    while (!_go) {                                                            \
      asm volatile("{\n\t.reg .pred P;\n\t"                                   \
        "mbarrier.try_wait.parity.acquire.cluster.shared::cta.b64 P, [%1], %2, 0x989680;\n\t" \
        "selp.b32 %0, 1, 0, P;\n\t}" : "=r"(_go) : "r"(mba), "r"(par) : "memory"); \
    }                                                                         \
} while (0)

// W3s[n][k] = W3[n][k] + W3[n][512+k]; b1s = bih1 + bhh1
__global__ void prep_kernel(const float* __restrict__ W3,
                            const float* __restrict__ bih1, const float* __restrict__ bhh1) {
    int idx = blockIdx.x * 256 + threadIdx.x;
    for (int i = idx; i < 1024 * 512; i += gridDim.x * 256) {
        int n = i >> 9, k = i & 511;
        g_W3s[i] = W3[n * 1024 + k] + W3[n * 1024 + 512 + k];
    }
    if (idx < 2048) g_b1s[idx] = bih1[idx] + bhh1[idx];
}

__global__ void pre0_kernel(const float* __restrict__ vr, const float* __restrict__ vl,
                            const float* __restrict__ Wih0,
                            const float* __restrict__ bih0, const float* __restrict__ bhh0) {
    __shared__ float vs[22];
    int row = blockIdx.x;
    int col = blockIdx.y * 128 + threadIdx.x;
    int seq = (row >= 384) ? 1 : 0;
    int t = row - seq * 384;
    const float* v = seq ? vl : vr;
    if (threadIdx.x < 22) vs[threadIdx.x] = v[t * 22 + threadIdx.x];
    __syncthreads();
    const float* w = Wih0 + (size_t)col * 22;
    float acc = bih0[col] + bhh0[col];
#pragma unroll
    for (int k = 0; k < 22; k++) acc += vs[k] * w[k];
    g_pre0[(size_t)row * PRE_W + col] = acc;
}

// 4 chains (seq,dir), 16-CTA cluster per chain (nonportable size). rank owns
// hidden units [16r, 16r+16) = 64 gate rows. 256 thr: out = tid>>2 (gidx*16+e),
// seg = tid&3 (64-wide k segment), 64 scalar weights in regs. Per-SMSP FFMA floor
// halves vs the 8-CTA version (2 warps x 64 FFMA). R13 handshake verbatim:
// single-warp mbarrier wait + __syncthreads release, hoisted mapa, lane-r arrives
// at peer r (count 16), last-step skip, exit cluster fence.
__global__ void __cluster_dims__(CS, 1, 1) __launch_bounds__(256, 1)
lstm_kernel(const float* __restrict__ Whh, int layer) {
    __shared__ __align__(16) float hbuf[2][4 * 72];   // 256 h per buffer, seg stride 72
    __shared__ float gates[64];
    __shared__ __align__(8) unsigned long long mb[2];

    const float* pre = layer ? g_pre1 : g_pre0;
    float* outp      = layer ? g_lout : g_x1;

    int tid = threadIdx.x;
    int rank = blockIdx.x & (CS - 1);
    int chain = blockIdx.x / CS;
    int seq = chain >> 1, dir = chain & 1;
    int out = tid >> 2, seg = tid & 3;
    int gidx = out >> 4, e = out & 15;
    int row = gidx * 256 + rank * 16 + e;

    // 64 scalar weights in registers
    float w[64];
    {
        const float* wp = Whh + ((size_t)dir * 1024 + row) * 256 + seg * 64;
#pragma unroll
        for (int j = 0; j < 64; j += 4) {
            float4 t4 = *(const float4*)(wp + j);
            w[j] = t4.x; w[j+1] = t4.y; w[j+2] = t4.z; w[j+3] = t4.w;
        }
    }
    for (int i = tid; i < 2 * 4 * 72; i += 256) ((float*)hbuf)[i] = 0.0f;
    if (tid == 0) {
        uint32_t m0 = (uint32_t)__cvta_generic_to_shared(&mb[0]);
        asm volatile("mbarrier.init.shared.b64 [%0], %1;" :: "r"(m0), "r"(CS) : "memory");
        asm volatile("mbarrier.init.shared.b64 [%0], %1;" :: "r"(m0 + 8), "r"(CS) : "memory");
    }
    __syncthreads();
    asm volatile("barrier.cluster.arrive.aligned;" ::: "memory");
    asm volatile("barrier.cluster.wait.aligned;"   ::: "memory");

    uint32_t mbLocal = (uint32_t)__cvta_generic_to_shared(&mb[0]);
    // hoisted remote addresses (warp0 lanes 0..15):
    //   radr[r] = address of MY h slot inside peer r's hbuf[0]
    //   rmbL    = peer (tid)'s mb[0]
    uint32_t radr[CS];
    uint32_t rmbL = 0;
    if (tid < 16) {
        int k = rank * 16 + tid;
        uint32_t loc = (uint32_t)__cvta_generic_to_shared(
            &hbuf[0][(k >> 6) * 72 + (k & 63)]);
#pragma unroll
        for (int r = 0; r < CS; r++)
            asm("mapa.shared::cluster.u32 %0, %1, %2;" : "=r"(radr[r]) : "r"(loc), "r"(r));
        asm("mapa.shared::cluster.u32 %0, %1, %2;" : "=r"(rmbL) : "r"(mbLocal), "r"(tid));
    }

    float c = 0.0f;
    const float* preBase = pre + (size_t)(seq * T_SEQ) * PRE_W + dir * 1024 + row;
    float* outBase = outp + (size_t)(seq * T_SEQ) * 512 + dir * 256 + rank * 16;
    int ph0 = 0, ph1 = 0;

    int tt0 = dir ? (T_SEQ - 1) : 0;
    float pv = __ldg(preBase + (size_t)tt0 * PRE_W);

    for (int t = 0; t < T_SEQ; t++) {
        int b = t & 1;
        if (t > 0) {
            if (tid < 32) {                       // single-warp wait
                uint32_t mba = mbLocal + (uint32_t)(b * 8);
                int par = b ? ph1 : ph0;
                MBAR_WAIT(mba, par);
            }
            if (b) ph1 ^= 1; else ph0 ^= 1;
            __syncthreads();                      // release all warps; orders h reads
        }
        int tt = dir ? (T_SEQ - 1 - t) : t;
        float pvn = 0.0f;
        if (t + 1 < T_SEQ) {
            int ttn = dir ? (T_SEQ - 2 - t) : (t + 1);
            pvn = __ldg(preBase + (size_t)ttn * PRE_W);
        }

        // scalar-FFMA inner loop: 16x float4 LDS, 64 FFMA, 4 indep chains
        const float4* hp = (const float4*)&hbuf[b][seg * 72];
        float a0 = 0.f, a1 = 0.f, a2 = 0.f, a3 = 0.f;
#pragma unroll
        for (int j = 0; j < 16; j++) {
            float4 hv = hp[j];
            a0 += w[4*j+0] * hv.x;
            a1 += w[4*j+1] * hv.y;
            a2 += w[4*j+2] * hv.z;
            a3 += w[4*j+3] * hv.w;
        }
        float acc = (a0 + a1) + (a2 + a3);
        acc += __shfl_xor_sync(0xffffffffu, acc, 1);
        acc += __shfl_xor_sync(0xffffffffu, acc, 2);
        float x = acc + pv;
        float av = (gidx == 2) ? ftanh_(x) : fsig(x);
        if (seg == 0) gates[gidx * 16 + e] = av;
        __syncthreads();                          // gates barrier; orders my h-reads
                                                  // before my arrivals below
        if (tid < 16) {
            float gi = gates[tid], gf = gates[16 + tid], gg = gates[32 + tid], go = gates[48 + tid];
            c = gf * c + gi * gg;
            float hv = go * ftanh_(c);
            outBase[(size_t)tt * 512 + tid] = hv;
            if (t + 1 < T_SEQ) {
                uint32_t boff = (uint32_t)(((t + 1) & 1) * 1152);
                // 16 lanes send this CTA's 16-float slice (64B) to each peer
#pragma unroll
                for (int r = 0; r < CS; r++) {
                    asm volatile("st.shared::cluster.f32 [%0], %1;"
                                 :: "r"(radr[r] + boff), "f"(hv) : "memory");
                }
                asm volatile("mbarrier.arrive.release.cluster.shared::cluster.b64 _, [%0];"
                             :: "r"(rmbL + (uint32_t)(((t + 1) & 1) * 8)) : "memory");
            }
        }
        pv = pvn;
    }
    // exit fence: no CTA may leave while remote stores could target peer SMEM
    asm volatile("barrier.cluster.arrive.aligned;" ::: "memory");
    asm volatile("barrier.cluster.wait.aligned;"   ::: "memory");
}

// C[M,N] = epi(A[M,K] @ B[N,K]^T). MODE 0:+bias  1:relu(+bias)  2:0.5*acc + (row<384?bias:0)
template <int MODE>
__global__ void __launch_bounds__(256) gemm_kernel(
    const float* __restrict__ A, const float* __restrict__ B, const float* __restrict__ bias,
    float* __restrict__ C, int M, int N, int K) {
    __shared__ __align__(16) float As[16][68];
    __shared__ __align__(16) float Bs[16][68];
    int tid = threadIdx.x;
    int bm = blockIdx.y * 64, bn = blockIdx.x * 64;
    int tx = tid & 15, ty = tid >> 4;
    int lr = tid >> 2, lc = (tid & 3) * 4;

    const float* Ap = A + (size_t)(bm + lr) * K + lc;
    const float* Bp = B + (size_t)(bn + lr) * K + lc;
    float acc[4][4] = {};
    float4 ra = *(const float4*)Ap;
    float4 rb4 = *(const float4*)Bp;
    int nk = K >> 4;
    for (int kt = 0; kt < nk; kt++) {
        As[lc+0][lr] = ra.x; As[lc+1][lr] = ra.y; As[lc+2][lr] = ra.z; As[lc+3][lr] = ra.w;
        Bs[lc+0][lr] = rb4.x; Bs[lc+1][lr] = rb4.y; Bs[lc+2][lr] = rb4.z; Bs[lc+3][lr] = rb4.w;
        __syncthreads();
        if (kt + 1 < nk) {
            ra  = *(const float4*)(Ap + (kt + 1) * 16);
            rb4 = *(const float4*)(Bp + (kt + 1) * 16);
        }
#pragma unroll
        for (int kk = 0; kk < 16; kk++) {
            float4 a4 = *(const float4*)&As[kk][ty * 4];
            float4 b4 = *(const float4*)&Bs[kk][tx * 4];
            acc[0][0] += a4.x*b4.x; acc[0][1] += a4.x*b4.y; acc[0][2] += a4.x*b4.z; acc[0][3] += a4.x*b4.w;
            acc[1][0] += a4.y*b4.x; acc[1][1] += a4.y*b4.y; acc[1][2] += a4.y*b4.z; acc[1][3] += a4.y*b4.w;
            acc[2][0] += a4.z*b4.x; acc[2][1] += a4.z*b4.y; acc[2][2] += a4.z*b4.z; acc[2][3] += a4.z*b4.w;
            acc[3][0] += a4.w*b4.x; acc[3][1] += a4.w*b4.y; acc[3][2] += a4.w*b4.z; acc[3][3] += a4.w*b4.w;
        }
        __syncthreads();
    }
    float bj0 = bias[bn + tx*4 + 0], bj1 = bias[bn + tx*4 + 1];
    float bj2 = bias[bn + tx*4 + 2], bj3 = bias[bn + tx*4 + 3];
#pragma unroll
    for (int i = 0; i < 4; i++) {
        int grow = bm + ty * 4 + i;
        float4 o;
        if (MODE == 0) {
            o.x = acc[i][0]+bj0; o.y = acc[i][1]+bj1; o.z = acc[i][2]+bj2; o.w = acc[i][3]+bj3;
        } else if (MODE == 1) {
            o.x = fmaxf(acc[i][0]+bj0, 0.f); o.y = fmaxf(acc[i][1]+bj1, 0.f);
            o.z = fmaxf(acc[i][2]+bj2, 0.f); o.w = fmaxf(acc[i][3]+bj3, 0.f);
        } else {
            float sc = (grow < 384) ? 1.f : 0.f;
            o.x = 0.5f*acc[i][0] + sc*bj0; o.y = 0.5f*acc[i][1] + sc*bj1;
            o.z = 0.5f*acc[i][2] + sc*bj2; o.w = 0.5f*acc[i][3] + sc*bj3;
        }
        *(float4*)&C[(size_t)grow * N + bn + tx * 4] = o;
    }
}

// d(i,j) = sum_h relu(u[i,h]+u[384+j,h])*(Wout[1,h]-Wout[0,h]) + db; out = {-l, d-l}, l=log1pexp(d)
__global__ void __launch_bounds__(256) pair_kernel(
    const float* __restrict__ Wout, const float* __restrict__ bout, float* __restrict__ outp) {
    __shared__ __align__(16) float urs[16][136];
    __shared__ __align__(16) float uls[16][136];
    __shared__ __align__(16) float dws[128];
    int tid = threadIdx.x;
    int bi = blockIdx.y * 16, bj = blockIdx.x * 16;
    int ti = tid >> 4, tj = tid & 15;
    int lr = tid >> 4, lc = (tid & 15) * 8;
    float d = bout[1] - bout[0];
    for (int hc = 0; hc < 1024; hc += 128) {
        __syncthreads();
        *(float4*)&urs[lr][lc]   = *(const float4*)&g_u[(size_t)(bi + lr) * 1024 + hc + lc];
        *(float4*)&urs[lr][lc+4] = *(const float4*)&g_u[(size_t)(bi + lr) * 1024 + hc + lc + 4];
        *(float4*)&uls[lr][lc]   = *(const float4*)&g_u[(size_t)(384 + bj + lr) * 1024 + hc + lc];
        *(float4*)&uls[lr][lc+4] = *(const float4*)&g_u[(size_t)(384 + bj + lr) * 1024 + hc + lc + 4];
        if (tid < 128) dws[tid] = Wout[1024 + hc + tid] - Wout[hc + tid];
        __syncthreads();
#pragma unroll 8
        for (int k = 0; k < 128; k += 4) {
            float4 a = *(const float4*)&urs[ti][k];
            float4 b = *(const float4*)&uls[tj][k];
            float4 w4 = *(const float4*)&dws[k];
            d += fmaxf(a.x + b.x, 0.f) * w4.x;
            d += fmaxf(a.y + b.y, 0.f) * w4.y;
            d += fmaxf(a.z + b.z, 0.f) * w4.z;
            d += fmaxf(a.w + b.w, 0.f) * w4.w;
        }
    }
    float m = fmaxf(d, 0.f);
    float l = m + __logf(__expf(0.f - m) + __expf(d - m));
    float2 o; o.x = -l; o.y = d - l;
    *(float2*)&outp[((size_t)(bi + ti) * 384 + (bj + tj)) * 2] = o;
}

extern "C" void kernel_launch(void* const* d_in, const int* in_sizes, int n_in,
                              void* d_out, int out_size) {
    const float* v_r  = (const float*)d_in[0];
    const float* v_l  = (const float*)d_in[1];
    const float* Wih0 = (const float*)d_in[2];
    const float* Whh0 = (const float*)d_in[3];
    const float* bih0 = (const float*)d_in[4];
    const float* bhh0 = (const float*)d_in[5];
    const float* Wih1 = (const float*)d_in[6];
    const float* Whh1 = (const float*)d_in[7];
    const float* bih1 = (const float*)d_in[8];
    const float* bhh1 = (const float*)d_in[9];
    const float* W1   = (const float*)d_in[10];
    const float* b1   = (const float*)d_in[11];
    const float* W2   = (const float*)d_in[12];
    const float* b2   = (const float*)d_in[13];
    const float* W3   = (const float*)d_in[14];
    const float* b3   = (const float*)d_in[15];
    const float* Wout = (const float*)d_in[16];
    const float* bout = (const float*)d_in[17];
    float* outp = (float*)d_out;

    // opt in to 16-CTA (nonportable) clusters; idempotent + deterministic
    cudaFuncSetAttribute(lstm_kernel, cudaFuncAttributeNonPortableClusterSizeAllowed, 1);

    void *p_x1, *p_lout, *p_h1, *p_h2, *p_u, *p_W3s, *p_b1s, *p_pre1;
    cudaGetSymbolAddress(&p_x1,   g_x1);
    cudaGetSymbolAddress(&p_lout, g_lout);
    cudaGetSymbolAddress(&p_h1,   g_h1);
    cudaGetSymbolAddress(&p_h2,   g_h2);
    cudaGetSymbolAddress(&p_u,    g_u);
    cudaGetSymbolAddress(&p_W3s,  g_W3s);
    cudaGetSymbolAddress(&p_b1s,  g_b1s);
    cudaGetSymbolAddress(&p_pre1, g_pre1);

    prep_kernel<<<148, 256>>>(W3, bih1, bhh1);
    pre0_kernel<<<dim3(ROWS_TOT, 16), 128>>>(v_r, v_l, Wih0, bih0, bhh0);
    lstm_kernel<<<4 * CS, 256>>>(Whh0, 0);
    gemm_kernel<0><<<dim3(32, 12), 256>>>((const float*)p_x1, Wih1, (const float*)p_b1s,
                                          (float*)p_pre1, 768, 2048, 512);
    lstm_kernel<<<4 * CS, 256>>>(Whh1, 1);
    gemm_kernel<1><<<dim3(16, 12), 256>>>((const float*)p_lout, W1, b1,
                                          (float*)p_h1, 768, 1024, 512);
    gemm_kernel<1><<<dim3(8, 12), 256>>>((const float*)p_h1, W2, b2,
                                         (float*)p_h2, 768, 512, 1024);
    gemm_kernel<2><<<dim3(16, 12), 256>>>((const float*)p_h2, (const float*)p_W3s, b3,
                                          (float*)p_u, 768, 1024, 512);
    pair_kernel<<<dim3(24, 24), 256>>>(Wout, bout, outp);
}